// round 1
// baseline (speedup 1.0000x reference)
#include <cuda_runtime.h>
#include <cuda_bf16.h>
#include <math.h>

#define N_NODES 4096
#define F_IN    64
#define HD      128
#define NH      8
#define DH      16
#define FIN_HD  192   // F + HD (W leading dim)

// ---------------- device scratch (no allocation allowed) ----------------
static __device__ float g_h  [N_NODES * HD];            // DCRNN hidden  [N,128]
static __device__ float g_q  [NH * N_NODES * DH];       // [head][n][dh]
static __device__ float g_k  [NH * N_NODES * DH];
static __device__ float g_v  [NH * N_NODES * DH];
static __device__ float g_ctx[N_NODES * HD];            // attention ctx [N,128] (interleaved heads)

// =====================================================================
// K1: h = (1 - sigmoid(x@Wz_eff + bz)) * tanh(x@Wh_eff + bh)
//     Wz_eff[i][j] = Wz[0][i][j] + Wz[1][i][j]  (i < 64 only, H0 = 0)
// block: 128 threads (j = col), ROWS=16 rows of x per block
// =====================================================================
#define K1_ROWS 16
__global__ void __launch_bounds__(128) gate_kernel(
    const float* __restrict__ x,
    const float* __restrict__ Wz, const float* __restrict__ bz,
    const float* __restrict__ Wh, const float* __restrict__ bh)
{
    __shared__ float xs[K1_ROWS * F_IN];
    const int j  = threadIdx.x;           // 0..127
    const int n0 = blockIdx.x * K1_ROWS;

    // load x tile [16][64]
    for (int idx = j; idx < K1_ROWS * F_IN; idx += 128)
        xs[idx] = x[n0 * F_IN + idx];
    __syncthreads();

    float az[K1_ROWS], ah[K1_ROWS];
#pragma unroll
    for (int r = 0; r < K1_ROWS; r++) { az[r] = 0.f; ah[r] = 0.f; }

#pragma unroll 4
    for (int i = 0; i < F_IN; i++) {
        const float wz = Wz[i * HD + j] + Wz[FIN_HD * HD + i * HD + j];
        const float wh = Wh[i * HD + j] + Wh[FIN_HD * HD + i * HD + j];
#pragma unroll
        for (int r = 0; r < K1_ROWS; r++) {
            const float xv = xs[r * F_IN + i];
            az[r] = fmaf(xv, wz, az[r]);
            ah[r] = fmaf(xv, wh, ah[r]);
        }
    }

    const float bzj = bz[j], bhj = bh[j];
#pragma unroll
    for (int r = 0; r < K1_ROWS; r++) {
        const float zs = az[r] + bzj;
        const float z  = 1.f / (1.f + __expf(-zs));
        const float ht = tanhf(ah[r] + bhj);
        g_h[(n0 + r) * HD + j] = (1.f - z) * ht;
    }
}

// =====================================================================
// K2: qkv = h @ in_proj_w^T + in_proj_b, scattered to [head][n][dh]
// block: 384 threads (o = output col), ROWS=16 rows
// =====================================================================
#define K2_ROWS 16
__global__ void __launch_bounds__(384) qkv_kernel(
    const float* __restrict__ ipw, const float* __restrict__ ipb)
{
    __shared__ float hs[K2_ROWS * HD];
    const int o  = threadIdx.x;           // 0..383
    const int n0 = blockIdx.x * K2_ROWS;

    for (int idx = o; idx < K2_ROWS * HD; idx += 384)
        hs[idx] = g_h[n0 * HD + idx];
    __syncthreads();

    float acc[K2_ROWS];
#pragma unroll
    for (int r = 0; r < K2_ROWS; r++) acc[r] = 0.f;

    const float4* wrow = (const float4*)(ipw + o * HD);
#pragma unroll 4
    for (int d4 = 0; d4 < HD / 4; d4++) {
        const float4 w = __ldg(&wrow[d4]);
#pragma unroll
        for (int r = 0; r < K2_ROWS; r++) {
            const float4 hv = *(const float4*)&hs[r * HD + d4 * 4];
            acc[r] = fmaf(hv.x, w.x, acc[r]);
            acc[r] = fmaf(hv.y, w.y, acc[r]);
            acc[r] = fmaf(hv.z, w.z, acc[r]);
            acc[r] = fmaf(hv.w, w.w, acc[r]);
        }
    }

    const float b = ipb[o];
    float* dst;
    int oo = o;
    if (o < HD)            { dst = g_q; }
    else if (o < 2 * HD)   { dst = g_k; oo = o - HD; }
    else                   { dst = g_v; oo = o - 2 * HD; }
    const int head = oo >> 4, dh = oo & 15;
#pragma unroll
    for (int r = 0; r < K2_ROWS; r++)
        dst[head * (N_NODES * DH) + (n0 + r) * DH + dh] = acc[r] + b;
}

// =====================================================================
// K3: flash attention fp32. 1 thread = 1 query. K/V tiles in smem.
// grid: (N/128, NH), 128 threads.
// =====================================================================
#define KT 128
__global__ void __launch_bounds__(128) attn_kernel()
{
    __shared__ float Ks[KT * DH];
    __shared__ float Vs[KT * DH];

    const int head = blockIdx.y;
    const int n    = blockIdx.x * 128 + threadIdx.x;
    const int tid  = threadIdx.x;
    const float* Qh = g_q + head * (N_NODES * DH);
    const float* Kh = g_k + head * (N_NODES * DH);
    const float* Vh = g_v + head * (N_NODES * DH);

    // query in registers
    float4 q0 = *(const float4*)&Qh[n * DH + 0];
    float4 q1 = *(const float4*)&Qh[n * DH + 4];
    float4 q2 = *(const float4*)&Qh[n * DH + 8];
    float4 q3 = *(const float4*)&Qh[n * DH + 12];
    const float scale = 0.25f;  // 1/sqrt(16)
    q0.x *= scale; q0.y *= scale; q0.z *= scale; q0.w *= scale;
    q1.x *= scale; q1.y *= scale; q1.z *= scale; q1.w *= scale;
    q2.x *= scale; q2.y *= scale; q2.z *= scale; q2.w *= scale;
    q3.x *= scale; q3.y *= scale; q3.z *= scale; q3.w *= scale;

    float m = -1e30f, l = 0.f;
    float acc[DH];
#pragma unroll
    for (int d = 0; d < DH; d++) acc[d] = 0.f;

    for (int kt = 0; kt < N_NODES / KT; kt++) {
        __syncthreads();
        // load K,V tile (coalesced float4)
        const float4* ksrc = (const float4*)&Kh[kt * KT * DH];
        const float4* vsrc = (const float4*)&Vh[kt * KT * DH];
        float4* kdst = (float4*)Ks;
        float4* vdst = (float4*)Vs;
#pragma unroll
        for (int i = 0; i < (KT * DH / 4) / 128; i++) {
            kdst[tid + i * 128] = ksrc[tid + i * 128];
            vdst[tid + i * 128] = vsrc[tid + i * 128];
        }
        __syncthreads();

#pragma unroll 4
        for (int j = 0; j < KT; j++) {
            const float4* kp = (const float4*)&Ks[j * DH];
            const float4 k0 = kp[0], k1 = kp[1], k2 = kp[2], k3 = kp[3];
            float s = q0.x * k0.x;
            s = fmaf(q0.y, k0.y, s); s = fmaf(q0.z, k0.z, s); s = fmaf(q0.w, k0.w, s);
            s = fmaf(q1.x, k1.x, s); s = fmaf(q1.y, k1.y, s); s = fmaf(q1.z, k1.z, s); s = fmaf(q1.w, k1.w, s);
            s = fmaf(q2.x, k2.x, s); s = fmaf(q2.y, k2.y, s); s = fmaf(q2.z, k2.z, s); s = fmaf(q2.w, k2.w, s);
            s = fmaf(q3.x, k3.x, s); s = fmaf(q3.y, k3.y, s); s = fmaf(q3.z, k3.z, s); s = fmaf(q3.w, k3.w, s);

            float p;
            if (s > m) {
                const float c = __expf(m - s);
                m = s;
                l *= c;
#pragma unroll
                for (int d = 0; d < DH; d++) acc[d] *= c;
                p = 1.f;
            } else {
                p = __expf(s - m);
            }
            l += p;
            const float4* vp = (const float4*)&Vs[j * DH];
            const float4 v0 = vp[0], v1 = vp[1], v2 = vp[2], v3 = vp[3];
            acc[0]  = fmaf(p, v0.x, acc[0]);  acc[1]  = fmaf(p, v0.y, acc[1]);
            acc[2]  = fmaf(p, v0.z, acc[2]);  acc[3]  = fmaf(p, v0.w, acc[3]);
            acc[4]  = fmaf(p, v1.x, acc[4]);  acc[5]  = fmaf(p, v1.y, acc[5]);
            acc[6]  = fmaf(p, v1.z, acc[6]);  acc[7]  = fmaf(p, v1.w, acc[7]);
            acc[8]  = fmaf(p, v2.x, acc[8]);  acc[9]  = fmaf(p, v2.y, acc[9]);
            acc[10] = fmaf(p, v2.z, acc[10]); acc[11] = fmaf(p, v2.w, acc[11]);
            acc[12] = fmaf(p, v3.x, acc[12]); acc[13] = fmaf(p, v3.y, acc[13]);
            acc[14] = fmaf(p, v3.z, acc[14]); acc[15] = fmaf(p, v3.w, acc[15]);
        }
    }

    const float inv = 1.f / l;
    float* out = &g_ctx[n * HD + head * DH];
#pragma unroll
    for (int d4 = 0; d4 < 4; d4++) {
        float4 o4;
        o4.x = acc[d4 * 4 + 0] * inv;
        o4.y = acc[d4 * 4 + 1] * inv;
        o4.z = acc[d4 * 4 + 2] * inv;
        o4.w = acc[d4 * 4 + 3] * inv;
        *(float4*)&out[d4 * 4] = o4;
    }
}

// =====================================================================
// K4: epilogue. attn_out = ctx@Wout^T + bout; h2 = h + attn_out;
//     hf = relu(h2@fc1^T + b1); out = hf@fc2^T + b2
// block: 128 threads, 8 rows
// =====================================================================
#define K4_ROWS 8
__global__ void __launch_bounds__(128) epilogue_kernel(
    const float* __restrict__ opw, const float* __restrict__ opb,
    const float* __restrict__ f1w, const float* __restrict__ f1b,
    const float* __restrict__ f2w, const float* __restrict__ f2b,
    float* __restrict__ out)
{
    __shared__ float cs [K4_ROWS * HD];
    __shared__ float hs [K4_ROWS * HD];
    __shared__ float h2s[K4_ROWS * HD];
    __shared__ float hfs[K4_ROWS * HD];

    const int j  = threadIdx.x;
    const int n0 = blockIdx.x * K4_ROWS;

    for (int idx = j; idx < K4_ROWS * HD; idx += 128) {
        cs[idx] = g_ctx[n0 * HD + idx];
        hs[idx] = g_h [n0 * HD + idx];
    }
    __syncthreads();

    // stage A: out_proj + residual
    {
        float acc[K4_ROWS];
#pragma unroll
        for (int r = 0; r < K4_ROWS; r++) acc[r] = 0.f;
        const float4* wrow = (const float4*)(opw + j * HD);
#pragma unroll 4
        for (int d4 = 0; d4 < HD / 4; d4++) {
            const float4 w = __ldg(&wrow[d4]);
#pragma unroll
            for (int r = 0; r < K4_ROWS; r++) {
                const float4 c = *(const float4*)&cs[r * HD + d4 * 4];
                acc[r] = fmaf(c.x, w.x, acc[r]);
                acc[r] = fmaf(c.y, w.y, acc[r]);
                acc[r] = fmaf(c.z, w.z, acc[r]);
                acc[r] = fmaf(c.w, w.w, acc[r]);
            }
        }
        const float b = opb[j];
#pragma unroll
        for (int r = 0; r < K4_ROWS; r++)
            h2s[r * HD + j] = acc[r] + b + hs[r * HD + j];
    }
    __syncthreads();

    // stage B: fc1 + relu
    {
        float acc[K4_ROWS];
#pragma unroll
        for (int r = 0; r < K4_ROWS; r++) acc[r] = 0.f;
        const float4* wrow = (const float4*)(f1w + j * HD);
#pragma unroll 4
        for (int d4 = 0; d4 < HD / 4; d4++) {
            const float4 w = __ldg(&wrow[d4]);
#pragma unroll
            for (int r = 0; r < K4_ROWS; r++) {
                const float4 c = *(const float4*)&h2s[r * HD + d4 * 4];
                acc[r] = fmaf(c.x, w.x, acc[r]);
                acc[r] = fmaf(c.y, w.y, acc[r]);
                acc[r] = fmaf(c.z, w.z, acc[r]);
                acc[r] = fmaf(c.w, w.w, acc[r]);
            }
        }
        const float b = f1b[j];
#pragma unroll
        for (int r = 0; r < K4_ROWS; r++)
            hfs[r * HD + j] = fmaxf(acc[r] + b, 0.f);
    }
    __syncthreads();

    // stage C: fc2 reduction. 4 warps, each handles 2 rows.
    const int warp = j >> 5, lane = j & 31;
    const float b2 = f2b[0];
#pragma unroll
    for (int rr = 0; rr < 2; rr++) {
        const int r = warp * 2 + rr;
        float v = 0.f;
#pragma unroll
        for (int i = 0; i < 4; i++) {
            const int jj = lane + i * 32;
            v = fmaf(hfs[r * HD + jj], f2w[jj], v);
        }
#pragma unroll
        for (int off = 16; off > 0; off >>= 1)
            v += __shfl_xor_sync(0xFFFFFFFFu, v, off);
        if (lane == 0) out[n0 + r] = v + b2;
    }
}

// =====================================================================
extern "C" void kernel_launch(void* const* d_in, const int* in_sizes, int n_in,
                              void* d_out, int out_size)
{
    const float* x   = (const float*)d_in[0];
    // d_in[1] = edge_index (int32) — mathematically inert for K=1 DConv
    const float* Wz  = (const float*)d_in[2];
    const float* bz  = (const float*)d_in[3];
    // d_in[4], d_in[5] = Wr, br — unused (R * H0 = 0)
    const float* Wh  = (const float*)d_in[6];
    const float* bh  = (const float*)d_in[7];
    const float* ipw = (const float*)d_in[8];
    const float* ipb = (const float*)d_in[9];
    const float* opw = (const float*)d_in[10];
    const float* opb = (const float*)d_in[11];
    const float* f1w = (const float*)d_in[12];
    const float* f1b = (const float*)d_in[13];
    const float* f2w = (const float*)d_in[14];
    const float* f2b = (const float*)d_in[15];
    float* out = (float*)d_out;

    gate_kernel<<<N_NODES / K1_ROWS, 128>>>(x, Wz, bz, Wh, bh);
    qkv_kernel<<<N_NODES / K2_ROWS, 384>>>(ipw, ipb);
    dim3 g3(N_NODES / 128, NH);
    attn_kernel<<<g3, 128>>>();
    epilogue_kernel<<<N_NODES / K4_ROWS, 128>>>(opw, opb, f1w, f1b, f2w, f2b, out);
}

// round 2
// speedup vs baseline: 1.4627x; 1.4627x over previous
#include <cuda_runtime.h>
#include <cuda_bf16.h>
#include <math.h>

#define N_NODES 4096
#define F_IN    64
#define HD      128
#define NH      8
#define DH      16
#define FIN_HD  192   // F + HD (W leading dim)
#define SPLIT   4
#define NHN     (NH * N_NODES)

typedef unsigned long long u64;

// ---------------- packed f32x2 helpers (Blackwell FFMA2) ----------------
__device__ __forceinline__ u64 pack2(float lo, float hi) {
    u64 r; asm("mov.b64 %0, {%1,%2};" : "=l"(r) : "f"(lo), "f"(hi)); return r;
}
__device__ __forceinline__ float2 unpack2(u64 v) {
    float lo, hi; asm("mov.b64 {%0,%1}, %2;" : "=f"(lo), "=f"(hi) : "l"(v));
    return make_float2(lo, hi);
}
__device__ __forceinline__ u64 fma2(u64 a, u64 b, u64 c) {
    u64 d; asm("fma.rn.f32x2 %0, %1, %2, %3;" : "=l"(d) : "l"(a), "l"(b), "l"(c));
    return d;
}
__device__ __forceinline__ u64 mul2(u64 a, u64 b) {
    u64 d; asm("mul.rn.f32x2 %0, %1, %2;" : "=l"(d) : "l"(a), "l"(b));
    return d;
}

// ---------------- device scratch (no allocation allowed) ----------------
static __device__ float g_h  [N_NODES * HD];            // DCRNN hidden  [N,128]
static __device__ float g_q  [NH * N_NODES * DH];       // [head][n][dh]
static __device__ float g_k  [NH * N_NODES * DH];
static __device__ float g_v  [NH * N_NODES * DH];
static __device__ float g_ctx[N_NODES * HD];            // attention ctx [N,128]
static __device__ float g_pm [SPLIT * NHN];             // partial max (log2 domain)
static __device__ float g_pl [SPLIT * NHN];             // partial sum
static __device__ u64   g_pacc[SPLIT * 8 * NHN];        // partial acc (8 x f32x2)

// =====================================================================
// K1: h = (1 - sigmoid(x@Wz_eff + bz)) * tanh(x@Wh_eff + bh)
// =====================================================================
#define K1_ROWS 16
__global__ void __launch_bounds__(128) gate_kernel(
    const float* __restrict__ x,
    const float* __restrict__ Wz, const float* __restrict__ bz,
    const float* __restrict__ Wh, const float* __restrict__ bh)
{
    __shared__ float xs[K1_ROWS * F_IN];
    const int j  = threadIdx.x;
    const int n0 = blockIdx.x * K1_ROWS;

    for (int idx = j; idx < K1_ROWS * F_IN; idx += 128)
        xs[idx] = x[n0 * F_IN + idx];
    __syncthreads();

    // packed (az, ah) accumulator per row
    u64 a2[K1_ROWS];
#pragma unroll
    for (int r = 0; r < K1_ROWS; r++) a2[r] = pack2(0.f, 0.f);

#pragma unroll 4
    for (int i = 0; i < F_IN; i++) {
        const float wz = Wz[i * HD + j] + Wz[FIN_HD * HD + i * HD + j];
        const float wh = Wh[i * HD + j] + Wh[FIN_HD * HD + i * HD + j];
        const u64 w2 = pack2(wz, wh);
#pragma unroll
        for (int r = 0; r < K1_ROWS; r++) {
            const float xv = xs[r * F_IN + i];
            a2[r] = fma2(pack2(xv, xv), w2, a2[r]);
        }
    }

    const float bzj = bz[j], bhj = bh[j];
#pragma unroll
    for (int r = 0; r < K1_ROWS; r++) {
        const float2 a = unpack2(a2[r]);
        const float z  = 1.f / (1.f + __expf(-(a.x + bzj)));
        const float ht = tanhf(a.y + bhj);
        g_h[(n0 + r) * HD + j] = (1.f - z) * ht;
    }
}

// =====================================================================
// K2: qkv = h @ in_proj_w^T + in_proj_b, scattered to [head][n][dh]
// =====================================================================
#define K2_ROWS 16
__global__ void __launch_bounds__(384) qkv_kernel(
    const float* __restrict__ ipw, const float* __restrict__ ipb)
{
    __shared__ float hs[K2_ROWS * HD];
    const int o  = threadIdx.x;           // 0..383
    const int n0 = blockIdx.x * K2_ROWS;

    for (int idx = o; idx < K2_ROWS * HD; idx += 384)
        hs[idx] = g_h[n0 * HD + idx];
    __syncthreads();

    u64 acc2[K2_ROWS];
#pragma unroll
    for (int r = 0; r < K2_ROWS; r++) acc2[r] = pack2(0.f, 0.f);

    const u64* wrow = (const u64*)(ipw + o * HD);
    const u64* hsu  = (const u64*)hs;
#pragma unroll 8
    for (int d = 0; d < HD / 2; d++) {
        const u64 w2 = __ldg(&wrow[d]);
#pragma unroll
        for (int r = 0; r < K2_ROWS; r++)
            acc2[r] = fma2(hsu[r * (HD / 2) + d], w2, acc2[r]);
    }

    const float b = ipb[o];
    float* dst;
    int oo = o;
    if (o < HD)            { dst = g_q; }
    else if (o < 2 * HD)   { dst = g_k; oo = o - HD; }
    else                   { dst = g_v; oo = o - 2 * HD; }
    const int head = oo >> 4, dh = oo & 15;
#pragma unroll
    for (int r = 0; r < K2_ROWS; r++) {
        const float2 a = unpack2(acc2[r]);
        dst[head * (N_NODES * DH) + (n0 + r) * DH + dh] = a.x + a.y + b;
    }
}

// =====================================================================
// K3: split-KV flash attention, packed f32x2. 1 thread = 1 query.
// grid: (N/128, NH, SPLIT), 128 threads. exp in log2 domain.
// =====================================================================
#define KT 128
#define KEYS_PER_SPLIT (N_NODES / SPLIT)
__global__ void __launch_bounds__(128) attn_kernel()
{
    __shared__ float Ks[KT * DH];
    __shared__ float Vs[KT * DH];

    const int head  = blockIdx.y;
    const int split = blockIdx.z;
    const int n     = blockIdx.x * 128 + threadIdx.x;
    const int tid   = threadIdx.x;
    const float* Qh = g_q + head * (N_NODES * DH);
    const float* Kh = g_k + head * (N_NODES * DH) + split * KEYS_PER_SPLIT * DH;
    const float* Vh = g_v + head * (N_NODES * DH) + split * KEYS_PER_SPLIT * DH;

    // query packed, scaled by 1/sqrt(dh) * log2(e) (log2-domain softmax)
    u64 q2[8];
    {
        const float sc = 0.25f * 1.4426950408889634f;
        const float4* qp = (const float4*)&Qh[n * DH];
#pragma unroll
        for (int i = 0; i < 4; i++) {
            const float4 v = qp[i];
            q2[2 * i + 0] = pack2(v.x * sc, v.y * sc);
            q2[2 * i + 1] = pack2(v.z * sc, v.w * sc);
        }
    }

    float m = -1e30f, l = 0.f;
    u64 acc2[8];
#pragma unroll
    for (int i = 0; i < 8; i++) acc2[i] = pack2(0.f, 0.f);

    for (int kt = 0; kt < KEYS_PER_SPLIT / KT; kt++) {
        __syncthreads();
        const float4* ksrc = (const float4*)&Kh[kt * KT * DH];
        const float4* vsrc = (const float4*)&Vh[kt * KT * DH];
        float4* kdst = (float4*)Ks;
        float4* vdst = (float4*)Vs;
#pragma unroll
        for (int i = 0; i < (KT * DH / 4) / 128; i++) {
            kdst[tid + i * 128] = ksrc[tid + i * 128];
            vdst[tid + i * 128] = vsrc[tid + i * 128];
        }
        __syncthreads();

#pragma unroll 4
        for (int j = 0; j < KT; j++) {
            const u64* kp = (const u64*)&Ks[j * DH];
            u64 s2 = mul2(q2[0], kp[0]);
            s2 = fma2(q2[1], kp[1], s2);
            s2 = fma2(q2[2], kp[2], s2);
            s2 = fma2(q2[3], kp[3], s2);
            s2 = fma2(q2[4], kp[4], s2);
            s2 = fma2(q2[5], kp[5], s2);
            s2 = fma2(q2[6], kp[6], s2);
            s2 = fma2(q2[7], kp[7], s2);
            const float2 sp = unpack2(s2);
            const float s = sp.x + sp.y;

            float p;
            if (s > m) {
                const float c = exp2f(m - s);
                m = s;
                l *= c;
                const u64 c2 = pack2(c, c);
#pragma unroll
                for (int i = 0; i < 8; i++) acc2[i] = mul2(acc2[i], c2);
                p = 1.f;
            } else {
                p = exp2f(s - m);
            }
            l += p;
            const u64 p2 = pack2(p, p);
            const u64* vp = (const u64*)&Vs[j * DH];
#pragma unroll
            for (int i = 0; i < 8; i++) acc2[i] = fma2(p2, vp[i], acc2[i]);
        }
    }

    // write unnormalized partials
    const int hn = head * N_NODES + n;
    g_pm[split * NHN + hn] = m;
    g_pl[split * NHN + hn] = l;
#pragma unroll
    for (int i = 0; i < 8; i++)
        g_pacc[(split * 8 + i) * NHN + hn] = acc2[i];
}

// =====================================================================
// K3b: merge split-KV partials -> g_ctx
// =====================================================================
__global__ void __launch_bounds__(256) merge_kernel()
{
    const int hn = blockIdx.x * 256 + threadIdx.x;   // 0..NHN-1
    if (hn >= NHN) return;

    float m = -1e30f;
#pragma unroll
    for (int s = 0; s < SPLIT; s++) m = fmaxf(m, g_pm[s * NHN + hn]);

    float l = 0.f;
    float acc[DH];
#pragma unroll
    for (int d = 0; d < DH; d++) acc[d] = 0.f;

#pragma unroll
    for (int s = 0; s < SPLIT; s++) {
        const float w = exp2f(g_pm[s * NHN + hn] - m);
        l += g_pl[s * NHN + hn] * w;
#pragma unroll
        for (int i = 0; i < 8; i++) {
            const float2 a = unpack2(g_pacc[(s * 8 + i) * NHN + hn]);
            acc[2 * i + 0] += a.x * w;
            acc[2 * i + 1] += a.y * w;
        }
    }

    const float inv = 1.f / l;
    const int head = hn / N_NODES, n = hn % N_NODES;
    float* out = &g_ctx[n * HD + head * DH];
#pragma unroll
    for (int d4 = 0; d4 < 4; d4++) {
        float4 o4;
        o4.x = acc[d4 * 4 + 0] * inv;
        o4.y = acc[d4 * 4 + 1] * inv;
        o4.z = acc[d4 * 4 + 2] * inv;
        o4.w = acc[d4 * 4 + 3] * inv;
        *(float4*)&out[d4 * 4] = o4;
    }
}

// =====================================================================
// K4: epilogue (packed). out_proj + residual -> fc1+relu -> fc2
// =====================================================================
#define K4_ROWS 8
__global__ void __launch_bounds__(128) epilogue_kernel(
    const float* __restrict__ opw, const float* __restrict__ opb,
    const float* __restrict__ f1w, const float* __restrict__ f1b,
    const float* __restrict__ f2w, const float* __restrict__ f2b,
    float* __restrict__ out)
{
    __shared__ float cs [K4_ROWS * HD];
    __shared__ float hs [K4_ROWS * HD];
    __shared__ float h2s[K4_ROWS * HD];
    __shared__ float hfs[K4_ROWS * HD];

    const int j  = threadIdx.x;
    const int n0 = blockIdx.x * K4_ROWS;

    for (int idx = j; idx < K4_ROWS * HD; idx += 128) {
        cs[idx] = g_ctx[n0 * HD + idx];
        hs[idx] = g_h [n0 * HD + idx];
    }
    __syncthreads();

    // stage A: out_proj + residual
    {
        u64 acc2[K4_ROWS];
#pragma unroll
        for (int r = 0; r < K4_ROWS; r++) acc2[r] = pack2(0.f, 0.f);
        const u64* wrow = (const u64*)(opw + j * HD);
        const u64* csu  = (const u64*)cs;
#pragma unroll 8
        for (int d = 0; d < HD / 2; d++) {
            const u64 w2 = __ldg(&wrow[d]);
#pragma unroll
            for (int r = 0; r < K4_ROWS; r++)
                acc2[r] = fma2(csu[r * (HD / 2) + d], w2, acc2[r]);
        }
        const float b = opb[j];
#pragma unroll
        for (int r = 0; r < K4_ROWS; r++) {
            const float2 a = unpack2(acc2[r]);
            h2s[r * HD + j] = a.x + a.y + b + hs[r * HD + j];
        }
    }
    __syncthreads();

    // stage B: fc1 + relu
    {
        u64 acc2[K4_ROWS];
#pragma unroll
        for (int r = 0; r < K4_ROWS; r++) acc2[r] = pack2(0.f, 0.f);
        const u64* wrow = (const u64*)(f1w + j * HD);
        const u64* h2u  = (const u64*)h2s;
#pragma unroll 8
        for (int d = 0; d < HD / 2; d++) {
            const u64 w2 = __ldg(&wrow[d]);
#pragma unroll
            for (int r = 0; r < K4_ROWS; r++)
                acc2[r] = fma2(h2u[r * (HD / 2) + d], w2, acc2[r]);
        }
        const float b = f1b[j];
#pragma unroll
        for (int r = 0; r < K4_ROWS; r++) {
            const float2 a = unpack2(acc2[r]);
            hfs[r * HD + j] = fmaxf(a.x + a.y + b, 0.f);
        }
    }
    __syncthreads();

    // stage C: fc2 reduction. 4 warps, each handles 2 rows.
    const int warp = j >> 5, lane = j & 31;
    const float b2 = f2b[0];
#pragma unroll
    for (int rr = 0; rr < 2; rr++) {
        const int r = warp * 2 + rr;
        float v = 0.f;
#pragma unroll
        for (int i = 0; i < 4; i++) {
            const int jj = lane + i * 32;
            v = fmaf(hfs[r * HD + jj], f2w[jj], v);
        }
#pragma unroll
        for (int off = 16; off > 0; off >>= 1)
            v += __shfl_xor_sync(0xFFFFFFFFu, v, off);
        if (lane == 0) out[n0 + r] = v + b2;
    }
}

// =====================================================================
extern "C" void kernel_launch(void* const* d_in, const int* in_sizes, int n_in,
                              void* d_out, int out_size)
{
    const float* x   = (const float*)d_in[0];
    // d_in[1] = edge_index — inert for K=1 DConv
    const float* Wz  = (const float*)d_in[2];
    const float* bz  = (const float*)d_in[3];
    // d_in[4], d_in[5] = Wr, br — unused (R * H0 = 0)
    const float* Wh  = (const float*)d_in[6];
    const float* bh  = (const float*)d_in[7];
    const float* ipw = (const float*)d_in[8];
    const float* ipb = (const float*)d_in[9];
    const float* opw = (const float*)d_in[10];
    const float* opb = (const float*)d_in[11];
    const float* f1w = (const float*)d_in[12];
    const float* f1b = (const float*)d_in[13];
    const float* f2w = (const float*)d_in[14];
    const float* f2b = (const float*)d_in[15];
    float* out = (float*)d_out;

    gate_kernel<<<N_NODES / K1_ROWS, 128>>>(x, Wz, bz, Wh, bh);
    qkv_kernel<<<N_NODES / K2_ROWS, 384>>>(ipw, ipb);
    dim3 g3(N_NODES / 128, NH, SPLIT);
    attn_kernel<<<g3, 128>>>();
    merge_kernel<<<(NHN + 255) / 256, 256>>>();
    epilogue_kernel<<<N_NODES / K4_ROWS, 128>>>(opw, opb, f1w, f1b, f2w, f2b, out);
}